// round 4
// baseline (speedup 1.0000x reference)
#include <cuda_runtime.h>

#define B_  4
#define N_  1024
#define D_  1024
#define H_  16
#define HD_ 64
#define M_  (B_*N_)   // 4096 token rows

// Scratch (device globals — no runtime allocation allowed)
__device__ float g_xn [M_ * D_];        // LayerNorm output        [4096][1024]
__device__ float g_qkv[M_ * 3 * D_];    // QKV projection output   [4096][3072]
__device__ float g_att[M_ * D_];        // attention output        [4096][1024]

// ---------------------------------------------------------------------------
// LayerNorm: one block per token row, 256 threads, float4 per thread
// ---------------------------------------------------------------------------
__global__ __launch_bounds__(256) void ln_kernel(
    const float* __restrict__ x, const float* __restrict__ gamma,
    const float* __restrict__ beta, float* __restrict__ out)
{
    const int row = blockIdx.x;
    const int tid = threadIdx.x;
    const float4 v = reinterpret_cast<const float4*>(x)[row * (D_ / 4) + tid];

    __shared__ float red[8];
    float s = v.x + v.y + v.z + v.w;
#pragma unroll
    for (int o = 16; o > 0; o >>= 1) s += __shfl_xor_sync(0xffffffffu, s, o);
    if ((tid & 31) == 0) red[tid >> 5] = s;
    __syncthreads();
    float tot = 0.f;
#pragma unroll
    for (int i = 0; i < 8; i++) tot += red[i];
    const float mean = tot * (1.0f / D_);

    const float d0 = v.x - mean, d1 = v.y - mean, d2 = v.z - mean, d3 = v.w - mean;
    float sq = d0 * d0 + d1 * d1 + d2 * d2 + d3 * d3;
    __syncthreads();
#pragma unroll
    for (int o = 16; o > 0; o >>= 1) sq += __shfl_xor_sync(0xffffffffu, sq, o);
    if ((tid & 31) == 0) red[tid >> 5] = sq;
    __syncthreads();
    float vt = 0.f;
#pragma unroll
    for (int i = 0; i < 8; i++) vt += red[i];
    const float rstd = rsqrtf(vt * (1.0f / D_) + 1e-5f);

    const float4 g = reinterpret_cast<const float4*>(gamma)[tid];
    const float4 b = reinterpret_cast<const float4*>(beta)[tid];
    float4 o4;
    o4.x = d0 * rstd * g.x + b.x;
    o4.y = d1 * rstd * g.y + b.y;
    o4.z = d2 * rstd * g.z + b.z;
    o4.w = d3 * rstd * g.w + b.w;
    reinterpret_cast<float4*>(out)[row * (D_ / 4) + tid] = o4;
}

// ---------------------------------------------------------------------------
// SIMT GEMM: C[M_, NC] = A[M_, 1024] @ W[1024, NC]
// 128x128 block tile, K-step 8, 256 threads, 8x8 microtile.
// PROJ epilogue: += bias[col] + resid[row, col]
// ---------------------------------------------------------------------------
template <int NC, bool PROJ>
__global__ __launch_bounds__(256) void gemm_kernel(
    const float* __restrict__ A, const float* __restrict__ W,
    float* __restrict__ C, const float* __restrict__ bias,
    const float* __restrict__ resid)
{
    __shared__ float As[8][128];   // k-major A tile (transposed on store)
    __shared__ float Bs[8][128];
    const int tid = threadIdx.x;
    const int tx = tid & 15, ty = tid >> 4;
    const int rb = blockIdx.y, cb = blockIdx.x;
    const float* Ab = A + rb * 128 * D_;
    const float* Wb = W + cb * 128;

    float acc[8][8];
#pragma unroll
    for (int i = 0; i < 8; i++)
#pragma unroll
        for (int j = 0; j < 8; j++) acc[i][j] = 0.f;

    const int ar = tid >> 1, ac = (tid & 1) * 4;   // A: 128 rows x 8 k
    const int br = tid >> 5, bc = (tid & 31) * 4;  // B: 8 k x 128 cols

    for (int k0 = 0; k0 < D_; k0 += 8) {
        const float4 av = *reinterpret_cast<const float4*>(Ab + ar * D_ + k0 + ac);
        const float4 bv = *reinterpret_cast<const float4*>(Wb + (k0 + br) * NC + bc);
        __syncthreads();
        As[ac + 0][ar] = av.x; As[ac + 1][ar] = av.y;
        As[ac + 2][ar] = av.z; As[ac + 3][ar] = av.w;
        *reinterpret_cast<float4*>(&Bs[br][bc]) = bv;
        __syncthreads();
#pragma unroll
        for (int kk = 0; kk < 8; kk++) {
            const float4 a0 = *reinterpret_cast<const float4*>(&As[kk][ty * 4]);
            const float4 a1 = *reinterpret_cast<const float4*>(&As[kk][64 + ty * 4]);
            const float4 b0 = *reinterpret_cast<const float4*>(&Bs[kk][tx * 4]);
            const float4 b1 = *reinterpret_cast<const float4*>(&Bs[kk][64 + tx * 4]);
            const float a[8]  = {a0.x, a0.y, a0.z, a0.w, a1.x, a1.y, a1.z, a1.w};
            const float bb[8] = {b0.x, b0.y, b0.z, b0.w, b1.x, b1.y, b1.z, b1.w};
#pragma unroll
            for (int i = 0; i < 8; i++)
#pragma unroll
                for (int j = 0; j < 8; j++)
                    acc[i][j] = fmaf(a[i], bb[j], acc[i][j]);
        }
    }

#pragma unroll
    for (int i = 0; i < 8; i++) {
        const int r  = (i < 4) ? (ty * 4 + i) : (64 + ty * 4 + (i - 4));
        const int gr = rb * 128 + r;
#pragma unroll
        for (int jh = 0; jh < 2; jh++) {
            const int gc = cb * 128 + jh * 64 + tx * 4;
            float4 o;
            o.x = acc[i][jh * 4 + 0]; o.y = acc[i][jh * 4 + 1];
            o.z = acc[i][jh * 4 + 2]; o.w = acc[i][jh * 4 + 3];
            if (PROJ) {
                const float4 bz = *reinterpret_cast<const float4*>(bias + gc);
                const float4 rx = *reinterpret_cast<const float4*>(resid + gr * D_ + gc);
                o.x += bz.x + rx.x; o.y += bz.y + rx.y;
                o.z += bz.z + rx.z; o.w += bz.w + rx.w;
            }
            *reinterpret_cast<float4*>(C + gr * NC + gc) = o;
        }
    }
}

// ---------------------------------------------------------------------------
// Flash attention with spatial-sim bias.
// Block: 128 q-rows of one (b,h); loop over 8 key tiles of 128.
// 256 threads, 8x8 S microtile, 8x4 O microtile.
// Smem (floats): Qts 64x132 | Kts 64x132 | Vs 128x68 | Ps 128x132
// ---------------------------------------------------------------------------
#define QTS_OFF 0
#define KTS_OFF 8448
#define VS_OFF  16896
#define PS_OFF  25600
#define ATTN_SMEM_BYTES ((25600 + 128 * 132) * 4)   // 169984 B

__global__ __launch_bounds__(256) void attn_kernel(
    const float* __restrict__ qkv, const float* __restrict__ sim,
    const float* __restrict__ swlp, float* __restrict__ att)
{
    extern __shared__ float sh[];
    float* Qts = sh + QTS_OFF;  // [d][r], stride 132
    float* Kts = sh + KTS_OFF;  // [d][c], stride 132
    float* Vs  = sh + VS_OFF;   // [m][d], stride 68
    float* Ps  = sh + PS_OFF;   // [r][m], stride 132 (sim tile, then P)

    const int tid = threadIdx.x;
    const int tx = tid & 15, ty = tid >> 4;
    const int qb = blockIdx.x * 128;
    const int b  = blockIdx.y >> 4, h = blockIdx.y & 15;

    const float alpha = 1.f / (1.f + __expf(-(*swlp)));
    const float c1 = (1.f - alpha) * 0.125f;   // (1-alpha) * HD^-0.5
    const float c2 = alpha;

    // Load Q tile transposed: Qts[d][r]
    const float* qp = qkv + (b * N_ + qb) * 3 * D_ + h * HD_;
#pragma unroll 4
    for (int idx = tid; idx < 128 * 64; idx += 256) {
        const int r = idx >> 6, d = idx & 63;
        Qts[d * 132 + r] = qp[r * 3 * D_ + d];
    }

    float o[8][4], mr[8], lr[8];
    int rl[8];
#pragma unroll
    for (int i = 0; i < 8; i++) {
        mr[i] = -1e30f; lr[i] = 0.f;
        rl[i] = (i < 4) ? (ty * 4 + i) : (64 + ty * 4 + (i - 4));
#pragma unroll
        for (int j = 0; j < 4; j++) o[i][j] = 0.f;
    }

    for (int t = 0; t < 8; t++) {
        const int kb = t * 128;
        __syncthreads();   // previous tile fully consumed

        // K tile transposed
        const float* kp = qkv + (b * N_ + kb) * 3 * D_ + D_ + h * HD_;
#pragma unroll 4
        for (int idx = tid; idx < 128 * 64; idx += 256) {
            const int r = idx >> 6, d = idx & 63;
            Kts[d * 132 + r] = kp[r * 3 * D_ + d];
        }
        // V tile natural layout
        const float* vp = qkv + (b * N_ + kb) * 3 * D_ + 2 * D_ + h * HD_;
#pragma unroll 4
        for (int idx = tid; idx < 128 * 16; idx += 256) {
            const int r = idx >> 4, d4 = (idx & 15) * 4;
            *reinterpret_cast<float4*>(&Vs[r * 68 + d4]) =
                *reinterpret_cast<const float4*>(vp + r * 3 * D_ + d4);
        }
        // Stage spatial-sim tile into Ps
        const float* sp = sim + qb * N_ + kb;
#pragma unroll 4
        for (int idx = tid; idx < 128 * 32; idx += 256) {
            const int r = idx >> 5, c4 = (idx & 31) * 4;
            *reinterpret_cast<float4*>(&Ps[r * 132 + c4]) =
                *reinterpret_cast<const float4*>(sp + r * N_ + c4);
        }
        __syncthreads();

        // S = Q @ K^T  (128x128x64)
        float s[8][8];
#pragma unroll
        for (int i = 0; i < 8; i++)
#pragma unroll
            for (int j = 0; j < 8; j++) s[i][j] = 0.f;
#pragma unroll 4
        for (int d = 0; d < 64; d++) {
            const float4 a0 = *reinterpret_cast<const float4*>(&Qts[d * 132 + ty * 4]);
            const float4 a1 = *reinterpret_cast<const float4*>(&Qts[d * 132 + 64 + ty * 4]);
            const float4 b0 = *reinterpret_cast<const float4*>(&Kts[d * 132 + tx * 4]);
            const float4 b1 = *reinterpret_cast<const float4*>(&Kts[d * 132 + 64 + tx * 4]);
            const float a[8]  = {a0.x, a0.y, a0.z, a0.w, a1.x, a1.y, a1.z, a1.w};
            const float bb[8] = {b0.x, b0.y, b0.z, b0.w, b1.x, b1.y, b1.z, b1.w};
#pragma unroll
            for (int i = 0; i < 8; i++)
#pragma unroll
                for (int j = 0; j < 8; j++)
                    s[i][j] = fmaf(a[i], bb[j], s[i][j]);
        }

        // Blend with sim, online softmax (row stats across 16 tx lanes), P -> Ps
#pragma unroll
        for (int i = 0; i < 8; i++) {
            float* prow = Ps + rl[i] * 132;
            const float4 s0 = *reinterpret_cast<const float4*>(prow + tx * 4);
            const float4 s1 = *reinterpret_cast<const float4*>(prow + 64 + tx * 4);
            float z[8];
            z[0] = fmaf(s[i][0], c1, s0.x * c2);
            z[1] = fmaf(s[i][1], c1, s0.y * c2);
            z[2] = fmaf(s[i][2], c1, s0.z * c2);
            z[3] = fmaf(s[i][3], c1, s0.w * c2);
            z[4] = fmaf(s[i][4], c1, s1.x * c2);
            z[5] = fmaf(s[i][5], c1, s1.y * c2);
            z[6] = fmaf(s[i][6], c1, s1.z * c2);
            z[7] = fmaf(s[i][7], c1, s1.w * c2);
            float mx = z[0];
#pragma unroll
            for (int j = 1; j < 8; j++) mx = fmaxf(mx, z[j]);
#pragma unroll
            for (int off = 8; off > 0; off >>= 1)
                mx = fmaxf(mx, __shfl_xor_sync(0xffffffffu, mx, off, 16));
            const float mn = fmaxf(mr[i], mx);
            const float f = __expf(mr[i] - mn);
            mr[i] = mn;
            float p[8], ls = 0.f;
#pragma unroll
            for (int j = 0; j < 8; j++) { p[j] = __expf(z[j] - mn); ls += p[j]; }
#pragma unroll
            for (int off = 8; off > 0; off >>= 1)
                ls += __shfl_xor_sync(0xffffffffu, ls, off, 16);
            lr[i] = lr[i] * f + ls;
            o[i][0] *= f; o[i][1] *= f; o[i][2] *= f; o[i][3] *= f;
            const float4 p0 = {p[0], p[1], p[2], p[3]};
            const float4 p1 = {p[4], p[5], p[6], p[7]};
            *reinterpret_cast<float4*>(prow + tx * 4) = p0;
            *reinterpret_cast<float4*>(prow + 64 + tx * 4) = p1;
        }
        __syncthreads();

        // O += P @ V  (128x64x128)
#pragma unroll 2
        for (int m = 0; m < 128; m++) {
            const float4 v4 = *reinterpret_cast<const float4*>(&Vs[m * 68 + tx * 4]);
#pragma unroll
            for (int i = 0; i < 8; i++) {
                const float p = Ps[rl[i] * 132 + m];   // broadcast LDS
                o[i][0] = fmaf(p, v4.x, o[i][0]);
                o[i][1] = fmaf(p, v4.y, o[i][1]);
                o[i][2] = fmaf(p, v4.z, o[i][2]);
                o[i][3] = fmaf(p, v4.w, o[i][3]);
            }
        }
    }

#pragma unroll
    for (int i = 0; i < 8; i++) {
        const float inv = 1.f / lr[i];
        const float4 ov = {o[i][0] * inv, o[i][1] * inv, o[i][2] * inv, o[i][3] * inv};
        *reinterpret_cast<float4*>(
            att + (b * N_ + qb + rl[i]) * D_ + h * HD_ + tx * 4) = ov;
    }
}

// ---------------------------------------------------------------------------
extern "C" void kernel_launch(void* const* d_in, const int* in_sizes, int n_in,
                              void* d_out, int out_size)
{
    const float* x      = (const float*)d_in[0];
    const float* gamma  = (const float*)d_in[1];
    const float* beta   = (const float*)d_in[2];
    const float* w_qkv  = (const float*)d_in[3];
    const float* w_proj = (const float*)d_in[4];
    const float* b_proj = (const float*)d_in[5];
    const float* swl    = (const float*)d_in[6];
    const float* sim    = (const float*)d_in[7];
    float* out = (float*)d_out;

    float *xn, *qkvb, *attb;
    cudaGetSymbolAddress((void**)&xn,   g_xn);
    cudaGetSymbolAddress((void**)&qkvb, g_qkv);
    cudaGetSymbolAddress((void**)&attb, g_att);

    // 1. LayerNorm
    ln_kernel<<<M_, 256>>>(x, gamma, beta, xn);

    // 2. QKV projection: [4096,1024] @ [1024,3072]
    gemm_kernel<3 * D_, false><<<dim3(24, 32), 256>>>(xn, w_qkv, qkvb, nullptr, nullptr);

    // 3. Attention (flash, spatial-sim bias)
    cudaFuncSetAttribute(attn_kernel,
                         cudaFuncAttributeMaxDynamicSharedMemorySize,
                         ATTN_SMEM_BYTES);
    attn_kernel<<<dim3(8, 64), 256, ATTN_SMEM_BYTES>>>(qkvb, sim, swl, attb);

    // 4. Output projection + bias + residual -> d_out
    gemm_kernel<D_, true><<<dim3(8, 32), 256>>>(attb, w_proj, out, b_proj, x);
}

// round 5
// speedup vs baseline: 1.5631x; 1.5631x over previous
#include <cuda_runtime.h>
#include <cstdint>

#define B_  4
#define N_  1024
#define D_  1024
#define H_  16
#define HD_ 64
#define M_  (B_*N_)   // 4096 token rows

// Scratch (device globals — no runtime allocation allowed)
__device__ float g_xn [M_ * D_];        // LayerNorm output        [4096][1024]
__device__ float g_qkv[M_ * 3 * D_];    // QKV projection output   [4096][3072]
__device__ float g_att[M_ * D_];        // attention output        [4096][1024]

// ---------------------------------------------------------------------------
// LayerNorm: one block per token row, 256 threads, float4 per thread
// ---------------------------------------------------------------------------
__global__ __launch_bounds__(256) void ln_kernel(
    const float* __restrict__ x, const float* __restrict__ gamma,
    const float* __restrict__ beta, float* __restrict__ out)
{
    const int row = blockIdx.x;
    const int tid = threadIdx.x;
    const float4 v = reinterpret_cast<const float4*>(x)[row * (D_ / 4) + tid];

    __shared__ float red[8];
    float s = v.x + v.y + v.z + v.w;
#pragma unroll
    for (int o = 16; o > 0; o >>= 1) s += __shfl_xor_sync(0xffffffffu, s, o);
    if ((tid & 31) == 0) red[tid >> 5] = s;
    __syncthreads();
    float tot = 0.f;
#pragma unroll
    for (int i = 0; i < 8; i++) tot += red[i];
    const float mean = tot * (1.0f / D_);

    const float d0 = v.x - mean, d1 = v.y - mean, d2 = v.z - mean, d3 = v.w - mean;
    float sq = d0 * d0 + d1 * d1 + d2 * d2 + d3 * d3;
    __syncthreads();
#pragma unroll
    for (int o = 16; o > 0; o >>= 1) sq += __shfl_xor_sync(0xffffffffu, sq, o);
    if ((tid & 31) == 0) red[tid >> 5] = sq;
    __syncthreads();
    float vt = 0.f;
#pragma unroll
    for (int i = 0; i < 8; i++) vt += red[i];
    const float rstd = rsqrtf(vt * (1.0f / D_) + 1e-5f);

    const float4 g = reinterpret_cast<const float4*>(gamma)[tid];
    const float4 b = reinterpret_cast<const float4*>(beta)[tid];
    float4 o4;
    o4.x = d0 * rstd * g.x + b.x;
    o4.y = d1 * rstd * g.y + b.y;
    o4.z = d2 * rstd * g.z + b.z;
    o4.w = d3 * rstd * g.w + b.w;
    reinterpret_cast<float4*>(out)[row * (D_ / 4) + tid] = o4;
}

// ---------------------------------------------------------------------------
// TF32 tensor-core GEMM: C[M_, NC] = A[M_, 1024] @ W[1024, NC]
// 128x128 block tile, K-step 16, 8 warps (2x4), warp tile 64x32,
// mma.sync.m16n8k8 tf32. PROJ epilogue: += bias[col] + resid[row, col].
// ---------------------------------------------------------------------------
__device__ __forceinline__ uint32_t f2tf32(float f) {
    uint32_t u;
    asm("cvt.rna.tf32.f32 %0, %1;" : "=r"(u) : "f"(f));
    return u;
}

__device__ __forceinline__ void mma_tf32(float* c, const uint32_t* a, const uint32_t* b) {
    asm volatile(
        "mma.sync.aligned.m16n8k8.row.col.f32.tf32.tf32.f32 "
        "{%0,%1,%2,%3}, {%4,%5,%6,%7}, {%8,%9}, {%0,%1,%2,%3};\n"
        : "+f"(c[0]), "+f"(c[1]), "+f"(c[2]), "+f"(c[3])
        : "r"(a[0]), "r"(a[1]), "r"(a[2]), "r"(a[3]), "r"(b[0]), "r"(b[1]));
}

#define AS_STRIDE 20    // conflict-free for a-frag pattern (m*20 mod 32 distinct)
#define BS_STRIDE 136   // conflict-free for b-frag pattern (k*136 mod 32 = 8k)

template <int NC, bool PROJ>
__global__ __launch_bounds__(256) void mma_gemm_kernel(
    const float* __restrict__ A, const float* __restrict__ W,
    float* __restrict__ C, const float* __restrict__ bias,
    const float* __restrict__ resid)
{
    __shared__ uint32_t As[128 * AS_STRIDE];   // tf32 bits, [m][k] row-major
    __shared__ uint32_t Bs[16 * BS_STRIDE];    // tf32 bits, [k][n] row-major

    const int tid  = threadIdx.x;
    const int lane = tid & 31;
    const int warp = tid >> 5;
    const int wm = (warp >> 2) * 64;    // warp row offset (0 or 64)
    const int wn = (warp & 3) * 32;     // warp col offset (0..96)
    const int l4 = lane & 3, l8 = lane >> 2;

    const int rb = blockIdx.y * 128;
    const int cb = blockIdx.x * 128;

    float c[4][4][4];
#pragma unroll
    for (int mi = 0; mi < 4; mi++)
#pragma unroll
        for (int ni = 0; ni < 4; ni++)
#pragma unroll
            for (int j = 0; j < 4; j++) c[mi][ni][j] = 0.f;

    // global-load index maps (2 float4 each for A-tile and W-tile)
    // A tile: 128 rows x 16 k; f: row = f>>2, kq = (f&3)*4
    // W tile: 16 k x 128 cols; f: kr = f>>5, c4 = (f&31)*4
    for (int k0 = 0; k0 < D_; k0 += 16) {
        float4 av[2], wv[2];
#pragma unroll
        for (int i = 0; i < 2; i++) {
            const int f = tid + i * 256;
            av[i] = *reinterpret_cast<const float4*>(
                A + (rb + (f >> 2)) * D_ + k0 + (f & 3) * 4);
            wv[i] = *reinterpret_cast<const float4*>(
                W + (k0 + (f >> 5)) * NC + cb + (f & 31) * 4);
        }
        __syncthreads();
#pragma unroll
        for (int i = 0; i < 2; i++) {
            const int f = tid + i * 256;
            uint4 at = {f2tf32(av[i].x), f2tf32(av[i].y), f2tf32(av[i].z), f2tf32(av[i].w)};
            uint4 wt = {f2tf32(wv[i].x), f2tf32(wv[i].y), f2tf32(wv[i].z), f2tf32(wv[i].w)};
            *reinterpret_cast<uint4*>(&As[(f >> 2) * AS_STRIDE + (f & 3) * 4]) = at;
            *reinterpret_cast<uint4*>(&Bs[(f >> 5) * BS_STRIDE + (f & 31) * 4]) = wt;
        }
        __syncthreads();

#pragma unroll
        for (int ks = 0; ks < 16; ks += 8) {
            uint32_t a[4][4], b[4][2];
#pragma unroll
            for (int mi = 0; mi < 4; mi++) {
                const int r = wm + mi * 16 + l8;
                a[mi][0] = As[r * AS_STRIDE + ks + l4];
                a[mi][1] = As[(r + 8) * AS_STRIDE + ks + l4];
                a[mi][2] = As[r * AS_STRIDE + ks + 4 + l4];
                a[mi][3] = As[(r + 8) * AS_STRIDE + ks + 4 + l4];
            }
#pragma unroll
            for (int ni = 0; ni < 4; ni++) {
                const int cc = wn + ni * 8 + l8;
                b[ni][0] = Bs[(ks + l4) * BS_STRIDE + cc];
                b[ni][1] = Bs[(ks + 4 + l4) * BS_STRIDE + cc];
            }
#pragma unroll
            for (int mi = 0; mi < 4; mi++)
#pragma unroll
                for (int ni = 0; ni < 4; ni++)
                    mma_tf32(c[mi][ni], a[mi], b[ni]);
        }
    }

    // Epilogue: c0,c1 -> (row, col..col+1); c2,c3 -> (row+8, col..col+1)
#pragma unroll
    for (int mi = 0; mi < 4; mi++) {
        const int r0 = rb + wm + mi * 16 + l8;
#pragma unroll
        for (int ni = 0; ni < 4; ni++) {
            const int col = cb + wn + ni * 8 + l4 * 2;
            float2 v0 = {c[mi][ni][0], c[mi][ni][1]};
            float2 v1 = {c[mi][ni][2], c[mi][ni][3]};
            if (PROJ) {
                const float2 bz = *reinterpret_cast<const float2*>(bias + col);
                const float2 r0x = *reinterpret_cast<const float2*>(resid + r0 * D_ + col);
                const float2 r1x = *reinterpret_cast<const float2*>(resid + (r0 + 8) * D_ + col);
                v0.x += bz.x + r0x.x; v0.y += bz.y + r0x.y;
                v1.x += bz.x + r1x.x; v1.y += bz.y + r1x.y;
            }
            *reinterpret_cast<float2*>(C + r0 * NC + col) = v0;
            *reinterpret_cast<float2*>(C + (r0 + 8) * NC + col) = v1;
        }
    }
}

// ---------------------------------------------------------------------------
// Flash attention with spatial-sim bias (SIMT, unchanged this round).
// Block: 128 q-rows of one (b,h); loop over 8 key tiles of 128.
// ---------------------------------------------------------------------------
#define QTS_OFF 0
#define KTS_OFF 8448
#define VS_OFF  16896
#define PS_OFF  25600
#define ATTN_SMEM_BYTES ((25600 + 128 * 132) * 4)   // 169984 B

__global__ __launch_bounds__(256) void attn_kernel(
    const float* __restrict__ qkv, const float* __restrict__ sim,
    const float* __restrict__ swlp, float* __restrict__ att)
{
    extern __shared__ float sh[];
    float* Qts = sh + QTS_OFF;  // [d][r], stride 132
    float* Kts = sh + KTS_OFF;  // [d][c], stride 132
    float* Vs  = sh + VS_OFF;   // [m][d], stride 68
    float* Ps  = sh + PS_OFF;   // [r][m], stride 132 (sim tile, then P)

    const int tid = threadIdx.x;
    const int tx = tid & 15, ty = tid >> 4;
    const int qb = blockIdx.x * 128;
    const int b  = blockIdx.y >> 4, h = blockIdx.y & 15;

    const float alpha = 1.f / (1.f + __expf(-(*swlp)));
    const float c1 = (1.f - alpha) * 0.125f;   // (1-alpha) * HD^-0.5
    const float c2 = alpha;

    // Load Q tile transposed: Qts[d][r]
    const float* qp = qkv + (b * N_ + qb) * 3 * D_ + h * HD_;
#pragma unroll 4
    for (int idx = tid; idx < 128 * 64; idx += 256) {
        const int r = idx >> 6, d = idx & 63;
        Qts[d * 132 + r] = qp[r * 3 * D_ + d];
    }

    float o[8][4], mr[8], lr[8];
    int rl[8];
#pragma unroll
    for (int i = 0; i < 8; i++) {
        mr[i] = -1e30f; lr[i] = 0.f;
        rl[i] = (i < 4) ? (ty * 4 + i) : (64 + ty * 4 + (i - 4));
#pragma unroll
        for (int j = 0; j < 4; j++) o[i][j] = 0.f;
    }

    for (int t = 0; t < 8; t++) {
        const int kb = t * 128;
        __syncthreads();   // previous tile fully consumed

        // K tile transposed
        const float* kp = qkv + (b * N_ + kb) * 3 * D_ + D_ + h * HD_;
#pragma unroll 4
        for (int idx = tid; idx < 128 * 64; idx += 256) {
            const int r = idx >> 6, d = idx & 63;
            Kts[d * 132 + r] = kp[r * 3 * D_ + d];
        }
        // V tile natural layout
        const float* vp = qkv + (b * N_ + kb) * 3 * D_ + 2 * D_ + h * HD_;
#pragma unroll 4
        for (int idx = tid; idx < 128 * 16; idx += 256) {
            const int r = idx >> 4, d4 = (idx & 15) * 4;
            *reinterpret_cast<float4*>(&Vs[r * 68 + d4]) =
                *reinterpret_cast<const float4*>(vp + r * 3 * D_ + d4);
        }
        // Stage spatial-sim tile into Ps
        const float* sp = sim + qb * N_ + kb;
#pragma unroll 4
        for (int idx = tid; idx < 128 * 32; idx += 256) {
            const int r = idx >> 5, c4 = (idx & 31) * 4;
            *reinterpret_cast<float4*>(&Ps[r * 132 + c4]) =
                *reinterpret_cast<const float4*>(sp + r * N_ + c4);
        }
        __syncthreads();

        // S = Q @ K^T  (128x128x64)
        float s[8][8];
#pragma unroll
        for (int i = 0; i < 8; i++)
#pragma unroll
            for (int j = 0; j < 8; j++) s[i][j] = 0.f;
#pragma unroll 4
        for (int d = 0; d < 64; d++) {
            const float4 a0 = *reinterpret_cast<const float4*>(&Qts[d * 132 + ty * 4]);
            const float4 a1 = *reinterpret_cast<const float4*>(&Qts[d * 132 + 64 + ty * 4]);
            const float4 b0 = *reinterpret_cast<const float4*>(&Kts[d * 132 + tx * 4]);
            const float4 b1 = *reinterpret_cast<const float4*>(&Kts[d * 132 + 64 + tx * 4]);
            const float a[8]  = {a0.x, a0.y, a0.z, a0.w, a1.x, a1.y, a1.z, a1.w};
            const float bb[8] = {b0.x, b0.y, b0.z, b0.w, b1.x, b1.y, b1.z, b1.w};
#pragma unroll
            for (int i = 0; i < 8; i++)
#pragma unroll
                for (int j = 0; j < 8; j++)
                    s[i][j] = fmaf(a[i], bb[j], s[i][j]);
        }

        // Blend with sim, online softmax (row stats across 16 tx lanes), P -> Ps
#pragma unroll
        for (int i = 0; i < 8; i++) {
            float* prow = Ps + rl[i] * 132;
            const float4 s0 = *reinterpret_cast<const float4*>(prow + tx * 4);
            const float4 s1 = *reinterpret_cast<const float4*>(prow + 64 + tx * 4);
            float z[8];
            z[0] = fmaf(s[i][0], c1, s0.x * c2);
            z[1] = fmaf(s[i][1], c1, s0.y * c2);
            z[2] = fmaf(s[i][2], c1, s0.z * c2);
            z[3] = fmaf(s[i][3], c1, s0.w * c2);
            z[4] = fmaf(s[i][4], c1, s1.x * c2);
            z[5] = fmaf(s[i][5], c1, s1.y * c2);
            z[6] = fmaf(s[i][6], c1, s1.z * c2);
            z[7] = fmaf(s[i][7], c1, s1.w * c2);
            float mx = z[0];
#pragma unroll
            for (int j = 1; j < 8; j++) mx = fmaxf(mx, z[j]);
#pragma unroll
            for (int off = 8; off > 0; off >>= 1)
                mx = fmaxf(mx, __shfl_xor_sync(0xffffffffu, mx, off, 16));
            const float mn = fmaxf(mr[i], mx);
            const float f = __expf(mr[i] - mn);
            mr[i] = mn;
            float p[8], ls = 0.f;
#pragma unroll
            for (int j = 0; j < 8; j++) { p[j] = __expf(z[j] - mn); ls += p[j]; }
#pragma unroll
            for (int off = 8; off > 0; off >>= 1)
                ls += __shfl_xor_sync(0xffffffffu, ls, off, 16);
            lr[i] = lr[i] * f + ls;
            o[i][0] *= f; o[i][1] *= f; o[i][2] *= f; o[i][3] *= f;
            const float4 p0 = {p[0], p[1], p[2], p[3]};
            const float4 p1 = {p[4], p[5], p[6], p[7]};
            *reinterpret_cast<float4*>(prow + tx * 4) = p0;
            *reinterpret_cast<float4*>(prow + 64 + tx * 4) = p1;
        }
        __syncthreads();

        // O += P @ V  (128x64x128)
#pragma unroll 2
        for (int m = 0; m < 128; m++) {
            const float4 v4 = *reinterpret_cast<const float4*>(&Vs[m * 68 + tx * 4]);
#pragma unroll
            for (int i = 0; i < 8; i++) {
                const float p = Ps[rl[i] * 132 + m];   // broadcast LDS
                o[i][0] = fmaf(p, v4.x, o[i][0]);
                o[i][1] = fmaf(p, v4.y, o[i][1]);
                o[i][2] = fmaf(p, v4.z, o[i][2]);
                o[i][3] = fmaf(p, v4.w, o[i][3]);
            }
        }
    }

#pragma unroll
    for (int i = 0; i < 8; i++) {
        const float inv = 1.f / lr[i];
        const float4 ov = {o[i][0] * inv, o[i][1] * inv, o[i][2] * inv, o[i][3] * inv};
        *reinterpret_cast<float4*>(
            att + (b * N_ + qb + rl[i]) * D_ + h * HD_ + tx * 4) = ov;
    }
}

// ---------------------------------------------------------------------------
extern "C" void kernel_launch(void* const* d_in, const int* in_sizes, int n_in,
                              void* d_out, int out_size)
{
    const float* x      = (const float*)d_in[0];
    const float* gamma  = (const float*)d_in[1];
    const float* beta   = (const float*)d_in[2];
    const float* w_qkv  = (const float*)d_in[3];
    const float* w_proj = (const float*)d_in[4];
    const float* b_proj = (const float*)d_in[5];
    const float* swl    = (const float*)d_in[6];
    const float* sim    = (const float*)d_in[7];
    float* out = (float*)d_out;

    float *xn, *qkvb, *attb;
    cudaGetSymbolAddress((void**)&xn,   g_xn);
    cudaGetSymbolAddress((void**)&qkvb, g_qkv);
    cudaGetSymbolAddress((void**)&attb, g_att);

    // 1. LayerNorm
    ln_kernel<<<M_, 256>>>(x, gamma, beta, xn);

    // 2. QKV projection: [4096,1024] @ [1024,3072]  (tf32 tensor cores)
    mma_gemm_kernel<3 * D_, false><<<dim3(24, 32), 256>>>(xn, w_qkv, qkvb, nullptr, nullptr);

    // 3. Attention (flash, spatial-sim bias)
    cudaFuncSetAttribute(attn_kernel,
                         cudaFuncAttributeMaxDynamicSharedMemorySize,
                         ATTN_SMEM_BYTES);
    attn_kernel<<<dim3(8, 64), 256, ATTN_SMEM_BYTES>>>(qkvb, sim, swl, attb);

    // 4. Output projection + bias + residual -> d_out  (tf32 tensor cores)
    mma_gemm_kernel<D_, true><<<dim3(8, 32), 256>>>(attb, w_proj, out, b_proj, x);
}

// round 6
// speedup vs baseline: 2.5473x; 1.6296x over previous
#include <cuda_runtime.h>
#include <cstdint>

#define B_  4
#define N_  1024
#define D_  1024
#define H_  16
#define HD_ 64
#define M_  (B_*N_)   // 4096 token rows

// Scratch (device globals — no runtime allocation allowed)
__device__ float g_xn [M_ * D_];        // LayerNorm output        [4096][1024]
__device__ float g_qkv[M_ * 3 * D_];    // QKV projection output   [4096][3072]
__device__ float g_att[M_ * D_];        // attention output        [4096][1024]

// ---------------------------------------------------------------------------
// Common tf32 helpers
// ---------------------------------------------------------------------------
__device__ __forceinline__ uint32_t f2tf32(float f) {
    uint32_t u;
    asm("cvt.rna.tf32.f32 %0, %1;" : "=r"(u) : "f"(f));
    return u;
}

__device__ __forceinline__ void mma_tf32(float* c, const uint32_t* a, const uint32_t* b) {
    asm volatile(
        "mma.sync.aligned.m16n8k8.row.col.f32.tf32.tf32.f32 "
        "{%0,%1,%2,%3}, {%4,%5,%6,%7}, {%8,%9}, {%0,%1,%2,%3};\n"
        : "+f"(c[0]), "+f"(c[1]), "+f"(c[2]), "+f"(c[3])
        : "r"(a[0]), "r"(a[1]), "r"(a[2]), "r"(a[3]), "r"(b[0]), "r"(b[1]));
}

// ---------------------------------------------------------------------------
// LayerNorm: one block per token row, 256 threads, float4 per thread
// ---------------------------------------------------------------------------
__global__ __launch_bounds__(256) void ln_kernel(
    const float* __restrict__ x, const float* __restrict__ gamma,
    const float* __restrict__ beta, float* __restrict__ out)
{
    const int row = blockIdx.x;
    const int tid = threadIdx.x;
    const float4 v = reinterpret_cast<const float4*>(x)[row * (D_ / 4) + tid];

    __shared__ float red[8];
    float s = v.x + v.y + v.z + v.w;
#pragma unroll
    for (int o = 16; o > 0; o >>= 1) s += __shfl_xor_sync(0xffffffffu, s, o);
    if ((tid & 31) == 0) red[tid >> 5] = s;
    __syncthreads();
    float tot = 0.f;
#pragma unroll
    for (int i = 0; i < 8; i++) tot += red[i];
    const float mean = tot * (1.0f / D_);

    const float d0 = v.x - mean, d1 = v.y - mean, d2 = v.z - mean, d3 = v.w - mean;
    float sq = d0 * d0 + d1 * d1 + d2 * d2 + d3 * d3;
    __syncthreads();
#pragma unroll
    for (int o = 16; o > 0; o >>= 1) sq += __shfl_xor_sync(0xffffffffu, sq, o);
    if ((tid & 31) == 0) red[tid >> 5] = sq;
    __syncthreads();
    float vt = 0.f;
#pragma unroll
    for (int i = 0; i < 8; i++) vt += red[i];
    const float rstd = rsqrtf(vt * (1.0f / D_) + 1e-5f);

    const float4 g = reinterpret_cast<const float4*>(gamma)[tid];
    const float4 b = reinterpret_cast<const float4*>(beta)[tid];
    float4 o4;
    o4.x = d0 * rstd * g.x + b.x;
    o4.y = d1 * rstd * g.y + b.y;
    o4.z = d2 * rstd * g.z + b.z;
    o4.w = d3 * rstd * g.w + b.w;
    reinterpret_cast<float4*>(out)[row * (D_ / 4) + tid] = o4;
}

// ---------------------------------------------------------------------------
// TF32 tensor-core GEMM: C[M_, NC] = A[M_, 1024] @ W[1024, NC]
// 128x128 block tile, K-step 16, 8 warps (2x4), warp tile 64x32.
// ---------------------------------------------------------------------------
#define AS_STRIDE 20
#define BS_STRIDE 136

template <int NC, bool PROJ>
__global__ __launch_bounds__(256) void mma_gemm_kernel(
    const float* __restrict__ A, const float* __restrict__ W,
    float* __restrict__ C, const float* __restrict__ bias,
    const float* __restrict__ resid)
{
    __shared__ uint32_t As[128 * AS_STRIDE];
    __shared__ uint32_t Bs[16 * BS_STRIDE];

    const int tid  = threadIdx.x;
    const int lane = tid & 31;
    const int warp = tid >> 5;
    const int wm = (warp >> 2) * 64;
    const int wn = (warp & 3) * 32;
    const int l4 = lane & 3, l8 = lane >> 2;

    const int rb = blockIdx.y * 128;
    const int cb = blockIdx.x * 128;

    float c[4][4][4];
#pragma unroll
    for (int mi = 0; mi < 4; mi++)
#pragma unroll
        for (int ni = 0; ni < 4; ni++)
#pragma unroll
            for (int j = 0; j < 4; j++) c[mi][ni][j] = 0.f;

    for (int k0 = 0; k0 < D_; k0 += 16) {
        float4 av[2], wv[2];
#pragma unroll
        for (int i = 0; i < 2; i++) {
            const int f = tid + i * 256;
            av[i] = *reinterpret_cast<const float4*>(
                A + (rb + (f >> 2)) * D_ + k0 + (f & 3) * 4);
            wv[i] = *reinterpret_cast<const float4*>(
                W + (k0 + (f >> 5)) * NC + cb + (f & 31) * 4);
        }
        __syncthreads();
#pragma unroll
        for (int i = 0; i < 2; i++) {
            const int f = tid + i * 256;
            uint4 at = {f2tf32(av[i].x), f2tf32(av[i].y), f2tf32(av[i].z), f2tf32(av[i].w)};
            uint4 wt = {f2tf32(wv[i].x), f2tf32(wv[i].y), f2tf32(wv[i].z), f2tf32(wv[i].w)};
            *reinterpret_cast<uint4*>(&As[(f >> 2) * AS_STRIDE + (f & 3) * 4]) = at;
            *reinterpret_cast<uint4*>(&Bs[(f >> 5) * BS_STRIDE + (f & 31) * 4]) = wt;
        }
        __syncthreads();

#pragma unroll
        for (int ks = 0; ks < 16; ks += 8) {
            uint32_t a[4][4], b[4][2];
#pragma unroll
            for (int mi = 0; mi < 4; mi++) {
                const int r = wm + mi * 16 + l8;
                a[mi][0] = As[r * AS_STRIDE + ks + l4];
                a[mi][1] = As[(r + 8) * AS_STRIDE + ks + l4];
                a[mi][2] = As[r * AS_STRIDE + ks + 4 + l4];
                a[mi][3] = As[(r + 8) * AS_STRIDE + ks + 4 + l4];
            }
#pragma unroll
            for (int ni = 0; ni < 4; ni++) {
                const int cc = wn + ni * 8 + l8;
                b[ni][0] = Bs[(ks + l4) * BS_STRIDE + cc];
                b[ni][1] = Bs[(ks + 4 + l4) * BS_STRIDE + cc];
            }
#pragma unroll
            for (int mi = 0; mi < 4; mi++)
#pragma unroll
                for (int ni = 0; ni < 4; ni++)
                    mma_tf32(c[mi][ni], a[mi], b[ni]);
        }
    }

#pragma unroll
    for (int mi = 0; mi < 4; mi++) {
        const int r0 = rb + wm + mi * 16 + l8;
#pragma unroll
        for (int ni = 0; ni < 4; ni++) {
            const int col = cb + wn + ni * 8 + l4 * 2;
            float2 v0 = {c[mi][ni][0], c[mi][ni][1]};
            float2 v1 = {c[mi][ni][2], c[mi][ni][3]};
            if (PROJ) {
                const float2 bz = *reinterpret_cast<const float2*>(bias + col);
                const float2 r0x = *reinterpret_cast<const float2*>(resid + r0 * D_ + col);
                const float2 r1x = *reinterpret_cast<const float2*>(resid + (r0 + 8) * D_ + col);
                v0.x += bz.x + r0x.x; v0.y += bz.y + r0x.y;
                v1.x += bz.x + r1x.x; v1.y += bz.y + r1x.y;
            }
            *reinterpret_cast<float2*>(C + r0 * NC + col) = v0;
            *reinterpret_cast<float2*>(C + (r0 + 8) * NC + col) = v1;
        }
    }
}

// ---------------------------------------------------------------------------
// TF32 mma flash attention with spatial-sim bias.
// Block = 128 q-rows of one (b,h); 8 warps, warp = 16 q-rows.
// Loop over 8 key tiles of 128. S via m16n8k8 (16 n-frags), online softmax in
// fragment registers, P -> warp-private smem (tf32), P@V via m16n8k8.
// Smem strides: conflict-free per-instruction for all frag load patterns.
// ---------------------------------------------------------------------------
#define ATT_QS 0                       // [128][68]  tf32
#define ATT_KS 8704                    // [64][136]  tf32, d-major (K^T)
#define ATT_VS 17408                   // [128][72]  tf32
#define ATT_PS 26624                   // [128][132] tf32 (warp-private rows)
#define ATT_SMEM_BYTES ((26624 + 128 * 132) * 4)   // 174080 B

__global__ __launch_bounds__(256, 1) void attn_mma_kernel(
    const float* __restrict__ qkv, const float* __restrict__ sim,
    const float* __restrict__ swlp, float* __restrict__ att)
{
    extern __shared__ uint32_t smu[];
    uint32_t* Qs = smu + ATT_QS;
    uint32_t* Ks = smu + ATT_KS;
    uint32_t* Vs = smu + ATT_VS;
    uint32_t* Ps = smu + ATT_PS;

    const int tid  = threadIdx.x;
    const int lane = tid & 31, warp = tid >> 5;
    const int l4 = lane & 3, l8 = lane >> 2;
    const int wm = warp * 16;
    const int qb = blockIdx.x * 128;
    const int b  = blockIdx.y >> 4, h = blockIdx.y & 15;

    const float alpha = 1.f / (1.f + __expf(-(*swlp)));
    const float c1 = (1.f - alpha) * 0.125f;
    const float c2 = alpha;

    // Q tile -> Qs (tf32, [r][d], stride 68)
    const float* qp = qkv + (size_t)(b * N_ + qb) * 3 * D_ + h * HD_;
#pragma unroll
    for (int i = 0; i < 8; i++) {
        const int idx = tid + i * 256;            // 128*16 float4 slots
        const int r = idx >> 4, c4 = (idx & 15) * 4;
        const float4 v = *reinterpret_cast<const float4*>(qp + r * 3 * D_ + c4);
        uint4 u = {f2tf32(v.x), f2tf32(v.y), f2tf32(v.z), f2tf32(v.w)};
        *reinterpret_cast<uint4*>(&Qs[r * 68 + c4]) = u;
    }

    float o[8][4];
#pragma unroll
    for (int ni = 0; ni < 8; ni++)
#pragma unroll
        for (int j = 0; j < 4; j++) o[ni][j] = 0.f;
    float m0 = -1e30f, m1 = -1e30f, l0 = 0.f, l1 = 0.f;

    for (int t = 0; t < 8; t++) {
        const int kb = t * 128;
        __syncthreads();    // prev tile's P@V reads of Vs done

        // K tile transposed -> Ks[d][key], stride 136
        const float* kp = qkv + (size_t)(b * N_ + kb) * 3 * D_ + D_ + h * HD_;
#pragma unroll 8
        for (int i = 0; i < 32; i++) {
            const int idx = tid + i * 256;        // 8192 scalars
            const int r = idx >> 6, d = idx & 63;
            Ks[d * 136 + r] = f2tf32(kp[r * 3 * D_ + d]);
        }
        // V tile -> Vs[key][d], stride 72
        const float* vp = qkv + (size_t)(b * N_ + kb) * 3 * D_ + 2 * D_ + h * HD_;
#pragma unroll
        for (int i = 0; i < 8; i++) {
            const int idx = tid + i * 256;
            const int r = idx >> 4, c4 = (idx & 15) * 4;
            const float4 v = *reinterpret_cast<const float4*>(vp + r * 3 * D_ + c4);
            uint4 u = {f2tf32(v.x), f2tf32(v.y), f2tf32(v.z), f2tf32(v.w)};
            *reinterpret_cast<uint4*>(&Vs[r * 72 + c4]) = u;
        }
        __syncthreads();

        // ---- S = Q @ K^T : 16 n-frags of m16n8, k = 64 ----
        float s[16][4];
#pragma unroll
        for (int ni = 0; ni < 16; ni++)
#pragma unroll
            for (int j = 0; j < 4; j++) s[ni][j] = 0.f;
#pragma unroll
        for (int ks = 0; ks < 64; ks += 8) {
            uint32_t a[4];
            a[0] = Qs[(wm + l8) * 68 + ks + l4];
            a[1] = Qs[(wm + l8 + 8) * 68 + ks + l4];
            a[2] = Qs[(wm + l8) * 68 + ks + 4 + l4];
            a[3] = Qs[(wm + l8 + 8) * 68 + ks + 4 + l4];
#pragma unroll
            for (int ni = 0; ni < 16; ni++) {
                uint32_t bf[2];
                bf[0] = Ks[(ks + l4) * 136 + ni * 8 + l8];
                bf[1] = Ks[(ks + 4 + l4) * 136 + ni * 8 + l8];
                mma_tf32(s[ni], a, bf);
            }
        }

        // ---- blend with sim (gmem, L2-resident) + online softmax ----
        const float* simp = sim + (size_t)(qb + wm + l8) * N_ + kb;
        float zx0 = -1e30f, zx1 = -1e30f;
#pragma unroll
        for (int ni = 0; ni < 16; ni++) {
            const float2 s0 = __ldg(reinterpret_cast<const float2*>(simp + ni * 8 + l4 * 2));
            const float2 s1 = __ldg(reinterpret_cast<const float2*>(simp + 8 * N_ + ni * 8 + l4 * 2));
            s[ni][0] = fmaf(s[ni][0], c1, s0.x * c2);
            s[ni][1] = fmaf(s[ni][1], c1, s0.y * c2);
            s[ni][2] = fmaf(s[ni][2], c1, s1.x * c2);
            s[ni][3] = fmaf(s[ni][3], c1, s1.y * c2);
            zx0 = fmaxf(zx0, fmaxf(s[ni][0], s[ni][1]));
            zx1 = fmaxf(zx1, fmaxf(s[ni][2], s[ni][3]));
        }
        zx0 = fmaxf(zx0, __shfl_xor_sync(0xffffffffu, zx0, 1));
        zx0 = fmaxf(zx0, __shfl_xor_sync(0xffffffffu, zx0, 2));
        zx1 = fmaxf(zx1, __shfl_xor_sync(0xffffffffu, zx1, 1));
        zx1 = fmaxf(zx1, __shfl_xor_sync(0xffffffffu, zx1, 2));

        const float mn0 = fmaxf(m0, zx0), mn1 = fmaxf(m1, zx1);
        const float f0 = __expf(m0 - mn0), f1 = __expf(m1 - mn1);
        m0 = mn0; m1 = mn1;

        float ls0 = 0.f, ls1 = 0.f;
        uint32_t* prow0 = Ps + (wm + l8) * 132;
        uint32_t* prow1 = Ps + (wm + l8 + 8) * 132;
#pragma unroll
        for (int ni = 0; ni < 16; ni++) {
            const float p0 = __expf(s[ni][0] - mn0);
            const float p1 = __expf(s[ni][1] - mn0);
            const float p2 = __expf(s[ni][2] - mn1);
            const float p3 = __expf(s[ni][3] - mn1);
            ls0 += p0 + p1; ls1 += p2 + p3;
            uint2 u0 = {f2tf32(p0), f2tf32(p1)};
            uint2 u1 = {f2tf32(p2), f2tf32(p3)};
            *reinterpret_cast<uint2*>(prow0 + ni * 8 + l4 * 2) = u0;
            *reinterpret_cast<uint2*>(prow1 + ni * 8 + l4 * 2) = u1;
        }
        ls0 += __shfl_xor_sync(0xffffffffu, ls0, 1);
        ls0 += __shfl_xor_sync(0xffffffffu, ls0, 2);
        ls1 += __shfl_xor_sync(0xffffffffu, ls1, 1);
        ls1 += __shfl_xor_sync(0xffffffffu, ls1, 2);
        l0 = l0 * f0 + ls0;
        l1 = l1 * f1 + ls1;

#pragma unroll
        for (int ni = 0; ni < 8; ni++) {
            o[ni][0] *= f0; o[ni][1] *= f0;
            o[ni][2] *= f1; o[ni][3] *= f1;
        }
        __syncwarp();   // P rows are warp-private; order writes before frag loads

        // ---- O += P @ V : 8 n-frags, k = 128 ----
#pragma unroll
        for (int ks = 0; ks < 128; ks += 8) {
            uint32_t a[4];
            a[0] = Ps[(wm + l8) * 132 + ks + l4];
            a[1] = Ps[(wm + l8 + 8) * 132 + ks + l4];
            a[2] = Ps[(wm + l8) * 132 + ks + 4 + l4];
            a[3] = Ps[(wm + l8 + 8) * 132 + ks + 4 + l4];
#pragma unroll
            for (int ni = 0; ni < 8; ni++) {
                uint32_t bf[2];
                bf[0] = Vs[(ks + l4) * 72 + ni * 8 + l8];
                bf[1] = Vs[(ks + 4 + l4) * 72 + ni * 8 + l8];
                mma_tf32(o[ni], a, bf);
            }
        }
    }

    // Epilogue: normalize and store
    const float inv0 = 1.f / l0, inv1 = 1.f / l1;
    float* op0 = att + (size_t)(b * N_ + qb + wm + l8) * D_ + h * HD_;
    float* op1 = op0 + 8 * D_;
#pragma unroll
    for (int ni = 0; ni < 8; ni++) {
        float2 v0 = {o[ni][0] * inv0, o[ni][1] * inv0};
        float2 v1 = {o[ni][2] * inv1, o[ni][3] * inv1};
        *reinterpret_cast<float2*>(op0 + ni * 8 + l4 * 2) = v0;
        *reinterpret_cast<float2*>(op1 + ni * 8 + l4 * 2) = v1;
    }
}

// ---------------------------------------------------------------------------
extern "C" void kernel_launch(void* const* d_in, const int* in_sizes, int n_in,
                              void* d_out, int out_size)
{
    const float* x      = (const float*)d_in[0];
    const float* gamma  = (const float*)d_in[1];
    const float* beta   = (const float*)d_in[2];
    const float* w_qkv  = (const float*)d_in[3];
    const float* w_proj = (const float*)d_in[4];
    const float* b_proj = (const float*)d_in[5];
    const float* swl    = (const float*)d_in[6];
    const float* sim    = (const float*)d_in[7];
    float* out = (float*)d_out;

    float *xn, *qkvb, *attb;
    cudaGetSymbolAddress((void**)&xn,   g_xn);
    cudaGetSymbolAddress((void**)&qkvb, g_qkv);
    cudaGetSymbolAddress((void**)&attb, g_att);

    // 1. LayerNorm
    ln_kernel<<<M_, 256>>>(x, gamma, beta, xn);

    // 2. QKV projection: [4096,1024] @ [1024,3072]  (tf32 tensor cores)
    mma_gemm_kernel<3 * D_, false><<<dim3(24, 32), 256>>>(xn, w_qkv, qkvb, nullptr, nullptr);

    // 3. Attention (flash, tf32 mma, spatial-sim bias)
    cudaFuncSetAttribute(attn_mma_kernel,
                         cudaFuncAttributeMaxDynamicSharedMemorySize,
                         ATT_SMEM_BYTES);
    attn_mma_kernel<<<dim3(8, 64), 256, ATT_SMEM_BYTES>>>(qkvb, sim, swl, attb);

    // 4. Output projection + bias + residual -> d_out  (tf32 tensor cores)
    mma_gemm_kernel<D_, true><<<dim3(8, 32), 256>>>(attb, w_proj, out, b_proj, x);
}

// round 7
// speedup vs baseline: 3.1349x; 1.2307x over previous
#include <cuda_runtime.h>
#include <cstdint>

#define B_  4
#define N_  1024
#define D_  1024
#define H_  16
#define HD_ 64
#define M_  (B_*N_)   // 4096 token rows

// Scratch (device globals — no runtime allocation allowed)
__device__ float g_xn [M_ * D_];        // LayerNorm output        [4096][1024]
__device__ float g_qkv[M_ * 3 * D_];    // QKV projection output   [4096][3072]
__device__ float g_att[M_ * D_];        // attention output        [4096][1024]

// ---------------------------------------------------------------------------
// Helpers: tf32 mma consumes raw fp32 bits (HW reads top 19 bits only);
// cp.async for direct gmem->smem staging.
// ---------------------------------------------------------------------------
__device__ __forceinline__ void mma_tf32(float* c, const uint32_t* a, const uint32_t* b) {
    asm volatile(
        "mma.sync.aligned.m16n8k8.row.col.f32.tf32.tf32.f32 "
        "{%0,%1,%2,%3}, {%4,%5,%6,%7}, {%8,%9}, {%0,%1,%2,%3};\n"
        : "+f"(c[0]), "+f"(c[1]), "+f"(c[2]), "+f"(c[3])
        : "r"(a[0]), "r"(a[1]), "r"(a[2]), "r"(a[3]), "r"(b[0]), "r"(b[1]));
}

__device__ __forceinline__ void cp16(void* smem_dst, const void* gmem_src) {
    const uint32_t s = (uint32_t)__cvta_generic_to_shared(smem_dst);
    asm volatile("cp.async.cg.shared.global [%0], [%1], 16;\n" :: "r"(s), "l"(gmem_src));
}
#define CP_COMMIT() asm volatile("cp.async.commit_group;\n" ::: "memory")
#define CP_WAIT(n)  asm volatile("cp.async.wait_group %0;\n" :: "n"(n) : "memory")

__device__ __forceinline__ uint32_t fu(float f) { return __float_as_uint(f); }

// ---------------------------------------------------------------------------
// LayerNorm: one block per token row, 256 threads, float4 per thread
// ---------------------------------------------------------------------------
__global__ __launch_bounds__(256) void ln_kernel(
    const float* __restrict__ x, const float* __restrict__ gamma,
    const float* __restrict__ beta, float* __restrict__ out)
{
    const int row = blockIdx.x;
    const int tid = threadIdx.x;
    const float4 v = reinterpret_cast<const float4*>(x)[row * (D_ / 4) + tid];

    __shared__ float red[8];
    float s = v.x + v.y + v.z + v.w;
#pragma unroll
    for (int o = 16; o > 0; o >>= 1) s += __shfl_xor_sync(0xffffffffu, s, o);
    if ((tid & 31) == 0) red[tid >> 5] = s;
    __syncthreads();
    float tot = 0.f;
#pragma unroll
    for (int i = 0; i < 8; i++) tot += red[i];
    const float mean = tot * (1.0f / D_);

    const float d0 = v.x - mean, d1 = v.y - mean, d2 = v.z - mean, d3 = v.w - mean;
    float sq = d0 * d0 + d1 * d1 + d2 * d2 + d3 * d3;
    __syncthreads();
#pragma unroll
    for (int o = 16; o > 0; o >>= 1) sq += __shfl_xor_sync(0xffffffffu, sq, o);
    if ((tid & 31) == 0) red[tid >> 5] = sq;
    __syncthreads();
    float vt = 0.f;
#pragma unroll
    for (int i = 0; i < 8; i++) vt += red[i];
    const float rstd = rsqrtf(vt * (1.0f / D_) + 1e-5f);

    const float4 g = reinterpret_cast<const float4*>(gamma)[tid];
    const float4 b = reinterpret_cast<const float4*>(beta)[tid];
    float4 o4;
    o4.x = d0 * rstd * g.x + b.x;
    o4.y = d1 * rstd * g.y + b.y;
    o4.z = d2 * rstd * g.z + b.z;
    o4.w = d3 * rstd * g.w + b.w;
    reinterpret_cast<float4*>(out)[row * (D_ / 4) + tid] = o4;
}

// ---------------------------------------------------------------------------
// TF32 tensor-core GEMM with cp.async double buffering.
// C[M_, NC] = A[M_, 1024] @ W[1024, NC]
// 128x128 block tile, K-step 32, 8 warps (2x4), warp tile 64x32.
// ---------------------------------------------------------------------------
#define AS_STRIDE 36    // 32 k + pad; frag pattern 4*l8+l4 conflict-free
#define BS_STRIDE 136   // 128 n + pad; frag pattern 8*k+n conflict-free

template <int NC, bool PROJ>
__global__ __launch_bounds__(256) void mma_gemm_kernel(
    const float* __restrict__ A, const float* __restrict__ W,
    float* __restrict__ C, const float* __restrict__ bias,
    const float* __restrict__ resid)
{
    __shared__ float As[2][128 * AS_STRIDE];
    __shared__ float Bs[2][32 * BS_STRIDE];

    const int tid  = threadIdx.x;
    const int lane = tid & 31;
    const int warp = tid >> 5;
    const int wm = (warp >> 2) * 64;
    const int wn = (warp & 3) * 32;
    const int l4 = lane & 3, l8 = lane >> 2;

    const int rb = blockIdx.y * 128;
    const int cb = blockIdx.x * 128;

    float c[4][4][4];
#pragma unroll
    for (int mi = 0; mi < 4; mi++)
#pragma unroll
        for (int ni = 0; ni < 4; ni++)
#pragma unroll
            for (int j = 0; j < 4; j++) c[mi][ni][j] = 0.f;

    // stage loader: A tile 128x32 (4 float4/thread), B tile 32x128 (4/thread)
    auto issue_tile = [&](int k0, int buf) {
#pragma unroll
        for (int i = 0; i < 4; i++) {
            const int f = tid + i * 256;
            cp16(&As[buf][(f >> 3) * AS_STRIDE + (f & 7) * 4],
                 A + (size_t)(rb + (f >> 3)) * D_ + k0 + (f & 7) * 4);
            cp16(&Bs[buf][(f >> 5) * BS_STRIDE + (f & 31) * 4],
                 W + (size_t)(k0 + (f >> 5)) * NC + cb + (f & 31) * 4);
        }
        CP_COMMIT();
    };

    issue_tile(0, 0);
    for (int it = 0; it < 32; ++it) {
        const int buf = it & 1;
        if (it < 31) { issue_tile((it + 1) * 32, buf ^ 1); CP_WAIT(1); }
        else         { CP_WAIT(0); }
        __syncthreads();

        const float* Ab = As[buf];
        const float* Bb = Bs[buf];
#pragma unroll
        for (int ks = 0; ks < 32; ks += 8) {
            uint32_t a[4][4], b[4][2];
#pragma unroll
            for (int mi = 0; mi < 4; mi++) {
                const int r = wm + mi * 16 + l8;
                a[mi][0] = fu(Ab[r * AS_STRIDE + ks + l4]);
                a[mi][1] = fu(Ab[(r + 8) * AS_STRIDE + ks + l4]);
                a[mi][2] = fu(Ab[r * AS_STRIDE + ks + 4 + l4]);
                a[mi][3] = fu(Ab[(r + 8) * AS_STRIDE + ks + 4 + l4]);
            }
#pragma unroll
            for (int ni = 0; ni < 4; ni++) {
                const int cc = wn + ni * 8 + l8;
                b[ni][0] = fu(Bb[(ks + l4) * BS_STRIDE + cc]);
                b[ni][1] = fu(Bb[(ks + 4 + l4) * BS_STRIDE + cc]);
            }
#pragma unroll
            for (int mi = 0; mi < 4; mi++)
#pragma unroll
                for (int ni = 0; ni < 4; ni++)
                    mma_tf32(c[mi][ni], a[mi], b[ni]);
        }
        __syncthreads();
    }

#pragma unroll
    for (int mi = 0; mi < 4; mi++) {
        const int r0 = rb + wm + mi * 16 + l8;
#pragma unroll
        for (int ni = 0; ni < 4; ni++) {
            const int col = cb + wn + ni * 8 + l4 * 2;
            float2 v0 = {c[mi][ni][0], c[mi][ni][1]};
            float2 v1 = {c[mi][ni][2], c[mi][ni][3]};
            if (PROJ) {
                const float2 bz = *reinterpret_cast<const float2*>(bias + col);
                const float2 r0x = *reinterpret_cast<const float2*>(resid + r0 * D_ + col);
                const float2 r1x = *reinterpret_cast<const float2*>(resid + (r0 + 8) * D_ + col);
                v0.x += bz.x + r0x.x; v0.y += bz.y + r0x.y;
                v1.x += bz.x + r1x.x; v1.y += bz.y + r1x.y;
            }
            *reinterpret_cast<float2*>(C + r0 * NC + col) = v0;
            *reinterpret_cast<float2*>(C + (r0 + 8) * NC + col) = v1;
        }
    }
}

// ---------------------------------------------------------------------------
// TF32 mma flash attention, cp.async pipelined, no K transpose.
// Block = 128 q-rows of one (b,h); 8 warps, warp = 16 q-rows; 8 key tiles.
// K stored natural [key][d] (stride 68) — b-frag pattern is conflict-free.
// K double-buffered (prefetched under softmax+P@V); V prefetched under S-mma.
// ---------------------------------------------------------------------------
#define ATT_QS 0                      // [128][68]
#define ATT_KS 8704                   // 2 x [128][68]
#define ATT_KSZ 8704
#define ATT_VS 26112                  // [128][72]
#define ATT_PS 35328                  // [128][132]
#define ATT_SMEM_BYTES ((35328 + 128 * 132) * 4)   // 208896 B

__global__ __launch_bounds__(256, 1) void attn_mma_kernel(
    const float* __restrict__ qkv, const float* __restrict__ sim,
    const float* __restrict__ swlp, float* __restrict__ att)
{
    extern __shared__ float sm[];
    float* Qs = sm + ATT_QS;
    float* Ks = sm + ATT_KS;
    float* Vs = sm + ATT_VS;
    float* Ps = sm + ATT_PS;

    const int tid  = threadIdx.x;
    const int lane = tid & 31, warp = tid >> 5;
    const int l4 = lane & 3, l8 = lane >> 2;
    const int wm = warp * 16;
    const int qb = blockIdx.x * 128;
    const int b  = blockIdx.y >> 4, h = blockIdx.y & 15;

    const float alpha = 1.f / (1.f + __expf(-(*swlp)));
    const float c1 = (1.f - alpha) * 0.125f;
    const float c2 = alpha;

    const float* qp    = qkv + (size_t)(b * N_ + qb) * 3 * D_ + h * HD_;
    const float* kbase = qkv + (size_t)(b * N_) * 3 * D_ + D_ + h * HD_;
    const float* vbase = qkv + (size_t)(b * N_) * 3 * D_ + 2 * D_ + h * HD_;

    // Prologue: Q tile + K(0) via cp.async (one group)
#pragma unroll
    for (int i = 0; i < 8; i++) {
        const int idx = tid + i * 256;            // 2048 float4 slots
        const int r = idx >> 4, c4 = (idx & 15) * 4;
        cp16(&Qs[r * 68 + c4], qp + (size_t)r * 3 * D_ + c4);
        cp16(&Ks[r * 68 + c4], kbase + (size_t)r * 3 * D_ + c4);
    }
    CP_COMMIT();

    float o[8][4];
#pragma unroll
    for (int ni = 0; ni < 8; ni++)
#pragma unroll
        for (int j = 0; j < 4; j++) o[ni][j] = 0.f;
    float m0 = -1e30f, m1 = -1e30f, l0 = 0.f, l1 = 0.f;

    for (int t = 0; t < 8; t++) {
        const int kb = t * 128;
        const float* Kc = Ks + (t & 1) * ATT_KSZ;

        __syncthreads();   // all warps done with Vs (prev P@V)

        // Issue V(t) — overlaps with S-mma below
#pragma unroll
        for (int i = 0; i < 8; i++) {
            const int idx = tid + i * 256;
            const int r = idx >> 4, c4 = (idx & 15) * 4;
            cp16(&Vs[r * 72 + c4], vbase + (size_t)(kb + r) * 3 * D_ + c4);
        }
        CP_COMMIT();

        CP_WAIT(1);        // K(t) [+Q] complete; V(t) still in flight
        __syncthreads();

        // ---- S = Q @ K^T : 16 n-frags of m16n8, k = 64 ----
        float s[16][4];
#pragma unroll
        for (int ni = 0; ni < 16; ni++)
#pragma unroll
            for (int j = 0; j < 4; j++) s[ni][j] = 0.f;
#pragma unroll
        for (int ks = 0; ks < 64; ks += 8) {
            uint32_t a[4];
            a[0] = fu(Qs[(wm + l8) * 68 + ks + l4]);
            a[1] = fu(Qs[(wm + l8 + 8) * 68 + ks + l4]);
            a[2] = fu(Qs[(wm + l8) * 68 + ks + 4 + l4]);
            a[3] = fu(Qs[(wm + l8 + 8) * 68 + ks + 4 + l4]);
#pragma unroll
            for (int ni = 0; ni < 16; ni++) {
                uint32_t bf[2];
                bf[0] = fu(Kc[(ni * 8 + l8) * 68 + ks + l4]);
                bf[1] = fu(Kc[(ni * 8 + l8) * 68 + ks + 4 + l4]);
                mma_tf32(s[ni], a, bf);
            }
        }

        // Prefetch K(t+1) into other buffer — overlaps softmax + P@V
        if (t < 7) {
            float* Kn = Ks + ((t + 1) & 1) * ATT_KSZ;
#pragma unroll
            for (int i = 0; i < 8; i++) {
                const int idx = tid + i * 256;
                const int r = idx >> 4, c4 = (idx & 15) * 4;
                cp16(&Kn[r * 68 + c4], kbase + (size_t)(kb + 128 + r) * 3 * D_ + c4);
            }
            CP_COMMIT();
            CP_WAIT(1);    // V(t) complete; K(t+1) in flight
        } else {
            CP_WAIT(0);
        }
        __syncthreads();   // Vs visible to all warps

        // ---- blend with sim (L2-resident gmem) + online softmax ----
        const float* simp = sim + (size_t)(qb + wm + l8) * N_ + kb;
        float zx0 = -1e30f, zx1 = -1e30f;
#pragma unroll
        for (int ni = 0; ni < 16; ni++) {
            const float2 s0 = __ldg(reinterpret_cast<const float2*>(simp + ni * 8 + l4 * 2));
            const float2 s1 = __ldg(reinterpret_cast<const float2*>(simp + 8 * N_ + ni * 8 + l4 * 2));
            s[ni][0] = fmaf(s[ni][0], c1, s0.x * c2);
            s[ni][1] = fmaf(s[ni][1], c1, s0.y * c2);
            s[ni][2] = fmaf(s[ni][2], c1, s1.x * c2);
            s[ni][3] = fmaf(s[ni][3], c1, s1.y * c2);
            zx0 = fmaxf(zx0, fmaxf(s[ni][0], s[ni][1]));
            zx1 = fmaxf(zx1, fmaxf(s[ni][2], s[ni][3]));
        }
        zx0 = fmaxf(zx0, __shfl_xor_sync(0xffffffffu, zx0, 1));
        zx0 = fmaxf(zx0, __shfl_xor_sync(0xffffffffu, zx0, 2));
        zx1 = fmaxf(zx1, __shfl_xor_sync(0xffffffffu, zx1, 1));
        zx1 = fmaxf(zx1, __shfl_xor_sync(0xffffffffu, zx1, 2));

        const float mn0 = fmaxf(m0, zx0), mn1 = fmaxf(m1, zx1);
        const float f0 = __expf(m0 - mn0), f1 = __expf(m1 - mn1);
        m0 = mn0; m1 = mn1;

        float ls0 = 0.f, ls1 = 0.f;
        float* prow0 = Ps + (wm + l8) * 132;
        float* prow1 = Ps + (wm + l8 + 8) * 132;
#pragma unroll
        for (int ni = 0; ni < 16; ni++) {
            const float p0 = __expf(s[ni][0] - mn0);
            const float p1 = __expf(s[ni][1] - mn0);
            const float p2 = __expf(s[ni][2] - mn1);
            const float p3 = __expf(s[ni][3] - mn1);
            ls0 += p0 + p1; ls1 += p2 + p3;
            *reinterpret_cast<float2*>(prow0 + ni * 8 + l4 * 2) = make_float2(p0, p1);
            *reinterpret_cast<float2*>(prow1 + ni * 8 + l4 * 2) = make_float2(p2, p3);
        }
        ls0 += __shfl_xor_sync(0xffffffffu, ls0, 1);
        ls0 += __shfl_xor_sync(0xffffffffu, ls0, 2);
        ls1 += __shfl_xor_sync(0xffffffffu, ls1, 1);
        ls1 += __shfl_xor_sync(0xffffffffu, ls1, 2);
        l0 = l0 * f0 + ls0;
        l1 = l1 * f1 + ls1;

#pragma unroll
        for (int ni = 0; ni < 8; ni++) {
            o[ni][0] *= f0; o[ni][1] *= f0;
            o[ni][2] *= f1; o[ni][3] *= f1;
        }
        __syncwarp();   // P rows warp-private: order stores before frag loads

        // ---- O += P @ V : 8 n-frags, k = 128 ----
#pragma unroll
        for (int ks = 0; ks < 128; ks += 8) {
            uint32_t a[4];
            a[0] = fu(Ps[(wm + l8) * 132 + ks + l4]);
            a[1] = fu(Ps[(wm + l8 + 8) * 132 + ks + l4]);
            a[2] = fu(Ps[(wm + l8) * 132 + ks + 4 + l4]);
            a[3] = fu(Ps[(wm + l8 + 8) * 132 + ks + 4 + l4]);
#pragma unroll
            for (int ni = 0; ni < 8; ni++) {
                uint32_t bf[2];
                bf[0] = fu(Vs[(ks + l4) * 72 + ni * 8 + l8]);
                bf[1] = fu(Vs[(ks + 4 + l4) * 72 + ni * 8 + l8]);
                mma_tf32(o[ni], a, bf);
            }
        }
    }

    // Epilogue: normalize and store
    const float inv0 = 1.f / l0, inv1 = 1.f / l1;
    float* op0 = att + (size_t)(b * N_ + qb + wm + l8) * D_ + h * HD_;
    float* op1 = op0 + 8 * D_;
#pragma unroll
    for (int ni = 0; ni < 8; ni++) {
        float2 v0 = {o[ni][0] * inv0, o[ni][1] * inv0};
        float2 v1 = {o[ni][2] * inv1, o[ni][3] * inv1};
        *reinterpret_cast<float2*>(op0 + ni * 8 + l4 * 2) = v0;
        *reinterpret_cast<float2*>(op1 + ni * 8 + l4 * 2) = v1;
    }
}

// ---------------------------------------------------------------------------
extern "C" void kernel_launch(void* const* d_in, const int* in_sizes, int n_in,
                              void* d_out, int out_size)
{
    const float* x      = (const float*)d_in[0];
    const float* gamma  = (const float*)d_in[1];
    const float* beta   = (const float*)d_in[2];
    const float* w_qkv  = (const float*)d_in[3];
    const float* w_proj = (const float*)d_in[4];
    const float* b_proj = (const float*)d_in[5];
    const float* swl    = (const float*)d_in[6];
    const float* sim    = (const float*)d_in[7];
    float* out = (float*)d_out;

    float *xn, *qkvb, *attb;
    cudaGetSymbolAddress((void**)&xn,   g_xn);
    cudaGetSymbolAddress((void**)&qkvb, g_qkv);
    cudaGetSymbolAddress((void**)&attb, g_att);

    // 1. LayerNorm
    ln_kernel<<<M_, 256>>>(x, gamma, beta, xn);

    // 2. QKV projection: [4096,1024] @ [1024,3072]  (tf32, cp.async pipelined)
    mma_gemm_kernel<3 * D_, false><<<dim3(24, 32), 256>>>(xn, w_qkv, qkvb, nullptr, nullptr);

    // 3. Attention (flash, tf32 mma, cp.async pipelined, spatial-sim bias)
    cudaFuncSetAttribute(attn_mma_kernel,
                         cudaFuncAttributeMaxDynamicSharedMemorySize,
                         ATT_SMEM_BYTES);
    attn_mma_kernel<<<dim3(8, 64), 256, ATT_SMEM_BYTES>>>(qkvb, sim, swl, attb);

    // 4. Output projection + bias + residual -> d_out  (tf32, cp.async pipelined)
    mma_gemm_kernel<D_, true><<<dim3(8, 32), 256>>>(attb, w_proj, out, b_proj, x);
}